// round 1
// baseline (speedup 1.0000x reference)
#include <cuda_runtime.h>
#include <float.h>

#define Bb 16
#define Ss 4096
#define Hh 1024
#define NN 2048
#define DWw 50
#define OD (Hh + DWw)   // 1074

__device__ float g_last_ctx[Bb * Hh];
__device__ float g_last_w[Bb * 64];

__device__ __forceinline__ void atomicMaxF(float* addr, float val) {
    if (val >= 0.f) atomicMax((int*)addr, __float_as_int(val));
    else            atomicMin((unsigned int*)addr, __float_as_uint(val));
}

__device__ __forceinline__ float4 fmax4(float4 a, float4 b) {
    a.x = fmaxf(a.x, b.x); a.y = fmaxf(a.y, b.y);
    a.z = fmaxf(a.z, b.z); a.w = fmaxf(a.w, b.w);
    return a;
}

__global__ void init_kernel() {
    int i = blockIdx.x * blockDim.x + threadIdx.x;
    float ninf = __int_as_float(0xFF800000);
    if (i < Bb * Hh) g_last_ctx[i] = ninf;
    if (i < Bb * 64) g_last_w[i] = ninf;
}

// last_ctx[b, :] = max over subwords 0..ns-2 of context_emb[b, s, :]
__global__ void lastctx_kernel(const float* __restrict__ ctx,
                               const int* __restrict__ ns_arr) {
    int b  = blockIdx.x;
    int rc = blockIdx.y;            // row chunk
    int t  = threadIdx.x;           // 0..255, owns channels 4t..4t+3
    int rows = ns_arr[b] - 1;       // subwords 0..rows-1
    int nch  = gridDim.y;
    int per  = (rows + nch - 1) / nch;
    int r0 = rc * per;
    int r1 = min(rows, r0 + per);
    if (r0 >= r1) return;

    const float4* base = (const float4*)(ctx + ((long)b * Ss + r0) * Hh);
    float4 acc = base[t];
    int cnt = r1 - r0;
#pragma unroll 4
    for (int r = 1; r < cnt; r++) {
        acc = fmax4(acc, base[(long)r * (Hh / 4) + t]);
    }
    float* dst = g_last_ctx + b * Hh + t * 4;
    atomicMaxF(dst + 0, acc.x);
    atomicMaxF(dst + 1, acc.y);
    atomicMaxF(dst + 2, acc.z);
    atomicMaxF(dst + 3, acc.w);
}

// last_w[b, :] = max over words 0..ns-1 of word_emb[b, n, :]
__global__ void lastw_kernel(const float* __restrict__ wemb,
                             const int* __restrict__ ns_arr) {
    int b  = blockIdx.x;
    int rc = blockIdx.y;
    int t  = threadIdx.x;           // 0..63
    if (t >= DWw) return;
    int rows = ns_arr[b];           // words 0..ns-1 inclusive
    int nch  = gridDim.y;
    int per  = (rows + nch - 1) / nch;
    int r0 = rc * per;
    int r1 = min(rows, r0 + per);
    if (r0 >= r1) return;

    float acc = wemb[((long)b * NN + r0) * DWw + t];
#pragma unroll 4
    for (int r = r0 + 1; r < r1; r++) {
        acc = fmaxf(acc, wemb[((long)b * NN + r) * DWw + t]);
    }
    atomicMaxF(&g_last_w[b * 64 + t], acc);
}

// One block per (b, n): segment max over the word's subword span + concat word_emb.
__global__ void main_kernel(const float* __restrict__ ctx,
                            const float* __restrict__ wemb,
                            const int* __restrict__ seg,
                            const int* __restrict__ ns_arr,
                            float* __restrict__ out) {
    int n = blockIdx.x;
    int b = blockIdx.y;
    int t = threadIdx.x;            // 0..255
    int ns = ns_arr[b];
    float* orow = out + ((long)b * NN + n) * OD;
    float2* o2 = (float2*)orow;     // rows are 8B-aligned (4296B stride)

    if (n >= ns) {
        // padding word: zero all 1074 floats (537 float2 slots)
        for (int i = t; i < OD / 2; i += 256) o2[i] = make_float2(0.f, 0.f);
        return;
    }
    if (n == ns - 1) {
        float4 v = ((const float4*)(g_last_ctx + b * Hh))[t];
        o2[2 * t]     = make_float2(v.x, v.y);
        o2[2 * t + 1] = make_float2(v.z, v.w);
        if (t < DWw) orow[Hh + t] = g_last_w[b * 64 + t];
        return;
    }

    // seg_ids[b,:] is sorted non-decreasing: span of word n = [lb(n), lb(n+1))
    __shared__ int sb[2];
    const float4* crow;
    {
        const int* s = seg + (long)b * Ss;
        if (t < 2) {
            int key = n + t;
            int lo = 0, hi = Ss;
            while (lo < hi) {
                int m = (lo + hi) >> 1;
                if (s[m] < key) lo = m + 1; else hi = m;
            }
            sb[t] = lo;
        }
    }
    __syncthreads();
    int start = sb[0];
    int end   = sb[1];

    crow = (const float4*)(ctx + ((long)b * Ss + start) * Hh);
    float4 acc = crow[t];
    int cnt = end - start;
#pragma unroll 2
    for (int r = 1; r < cnt; r++) {
        acc = fmax4(acc, crow[(long)r * (Hh / 4) + t]);
    }
    o2[2 * t]     = make_float2(acc.x, acc.y);
    o2[2 * t + 1] = make_float2(acc.z, acc.w);
    if (t < DWw) orow[Hh + t] = wemb[((long)b * NN + n) * DWw + t];
}

extern "C" void kernel_launch(void* const* d_in, const int* in_sizes, int n_in,
                              void* d_out, int out_size) {
    const float* ctx  = (const float*)d_in[0];   // [B, S, H]
    const float* wemb = (const float*)d_in[1];   // [B, N, DW]
    const int*   seg  = (const int*)d_in[2];     // [B, S]
    const int*   ns   = (const int*)d_in[3];     // [B]
    float* out = (float*)d_out;                  // [B, N, H+DW]

    init_kernel<<<(Bb * Hh + 255) / 256, 256>>>();
    lastctx_kernel<<<dim3(Bb, 32), 256>>>(ctx, ns);
    lastw_kernel<<<dim3(Bb, 32), 64>>>(wemb, ns);
    main_kernel<<<dim3(NN, Bb), 256>>>(ctx, wemb, seg, ns, out);
}

// round 2
// speedup vs baseline: 1.3517x; 1.3517x over previous
#include <cuda_runtime.h>

#define Bb 16
#define Ss 4096
#define Hh 1024
#define NN 2048
#define DWw 50
#define OD (Hh + DWw)   // 1074

#define NCH_CTX 64      // lastctx chunks per batch
#define NCH_W   8       // lastw chunks per batch
#define XTRA (NCH_CTX + NCH_W)

__device__ float g_last_ctx[Bb * Hh];
__device__ float g_last_w[Bb * 64];
__device__ int   g_start[Bb][NN + 1];

__device__ __forceinline__ void atomicMaxF(float* addr, float val) {
    if (val >= 0.f) atomicMax((int*)addr, __float_as_int(val));
    else            atomicMin((unsigned int*)addr, __float_as_uint(val));
}

__device__ __forceinline__ float4 fmax4(float4 a, float4 b) {
    a.x = fmaxf(a.x, b.x); a.y = fmaxf(a.y, b.y);
    a.z = fmaxf(a.z, b.z); a.w = fmaxf(a.w, b.w);
    return a;
}

// Pass 1: detect word-span boundaries from sorted seg_ids, init scratch.
__global__ void prep_kernel(const int* __restrict__ seg) {
    int b = blockIdx.x;
    int s = blockIdx.y * 256 + threadIdx.x;
    int v = seg[(long)b * Ss + s];
    int prev = (s == 0) ? -1 : seg[(long)b * Ss + s - 1];
    if (v != prev) g_start[b][v] = s;
    if (s == Ss - 1) g_start[b][v + 1] = Ss;   // sentinel end for last word

    if (blockIdx.y == 0) {
        float ninf = __int_as_float(0xFF800000);
        for (int i = threadIdx.x; i < Hh; i += 256) g_last_ctx[b * Hh + i] = ninf;
        if (threadIdx.x < 64) g_last_w[b * 64 + threadIdx.x] = ninf;
    }
}

// Pass 2 (fused): per-word segment max + output concat, plus lastctx/lastw
// reductions in extra blocks that stream concurrently.
__global__ void fused_kernel(const float* __restrict__ ctx,
                             const float* __restrict__ wemb,
                             const int* __restrict__ ns_arr,
                             float* __restrict__ out) {
    int bx = blockIdx.x;
    int b  = blockIdx.y;
    int t  = threadIdx.x;            // 0..255
    int ns = ns_arr[b];

    if (bx < NN) {
        int n = bx;
        float* orow = out + ((long)b * NN + n) * OD;
        float2* o2 = (float2*)orow;   // rows are 8B-aligned (4296B stride)

        if (n >= ns) {                // padding: zero-fill (out is poisoned)
            for (int i = t; i < OD / 2; i += 256) o2[i] = make_float2(0.f, 0.f);
            return;
        }
        if (n == ns - 1) return;      // written by finish_kernel

        int start = __ldg(&g_start[b][n]);
        int end   = __ldg(&g_start[b][n + 1]);

        const float4* crow = (const float4*)(ctx + ((long)b * Ss + start) * Hh);
        float4 acc = crow[t];
        int cnt = end - start;
#pragma unroll 4
        for (int r = 1; r < cnt; r++) {
            acc = fmax4(acc, crow[(long)r * (Hh / 4) + t]);
        }
        o2[2 * t]     = make_float2(acc.x, acc.y);
        o2[2 * t + 1] = make_float2(acc.z, acc.w);
        if (t < DWw) orow[Hh + t] = wemb[((long)b * NN + n) * DWw + t];
        return;
    }

    int rc = bx - NN;
    if (rc < NCH_CTX) {
        // lastctx: max over subwords 0..ns-2
        int rows = ns - 1;
        int per  = (rows + NCH_CTX - 1) / NCH_CTX;
        int r0 = rc * per;
        int r1 = min(rows, r0 + per);
        if (r0 >= r1) return;

        const float4* base = (const float4*)(ctx + ((long)b * Ss + r0) * Hh);
        float4 acc = base[t];
        int cnt = r1 - r0;
#pragma unroll 4
        for (int r = 1; r < cnt; r++) {
            acc = fmax4(acc, base[(long)r * (Hh / 4) + t]);
        }
        float* dst = g_last_ctx + b * Hh + t * 4;
        atomicMaxF(dst + 0, acc.x);
        atomicMaxF(dst + 1, acc.y);
        atomicMaxF(dst + 2, acc.z);
        atomicMaxF(dst + 3, acc.w);
    } else {
        // lastw: max over words 0..ns-1 of word_emb
        rc -= NCH_CTX;
        if (t >= DWw) return;
        int rows = ns;
        int per  = (rows + NCH_W - 1) / NCH_W;
        int r0 = rc * per;
        int r1 = min(rows, r0 + per);
        if (r0 >= r1) return;

        float acc = wemb[((long)b * NN + r0) * DWw + t];
#pragma unroll 4
        for (int r = r0 + 1; r < r1; r++) {
            acc = fmaxf(acc, wemb[((long)b * NN + r) * DWw + t]);
        }
        atomicMaxF(&g_last_w[b * 64 + t], acc);
    }
}

// Pass 3: write the special last-word row from the folded scratch.
__global__ void finish_kernel(const int* __restrict__ ns_arr,
                              float* __restrict__ out) {
    int b = blockIdx.x;
    int t = threadIdx.x;
    int n = ns_arr[b] - 1;
    float* orow = out + ((long)b * NN + n) * OD;
    float2* o2 = (float2*)orow;
    float4 v = ((const float4*)(g_last_ctx + b * Hh))[t];
    o2[2 * t]     = make_float2(v.x, v.y);
    o2[2 * t + 1] = make_float2(v.z, v.w);
    if (t < DWw) orow[Hh + t] = g_last_w[b * 64 + t];
}

extern "C" void kernel_launch(void* const* d_in, const int* in_sizes, int n_in,
                              void* d_out, int out_size) {
    const float* ctx  = (const float*)d_in[0];   // [B, S, H]
    const float* wemb = (const float*)d_in[1];   // [B, N, DW]
    const int*   seg  = (const int*)d_in[2];     // [B, S]
    const int*   ns   = (const int*)d_in[3];     // [B]
    float* out = (float*)d_out;                  // [B, N, H+DW]

    prep_kernel<<<dim3(Bb, Ss / 256), 256>>>(seg);
    fused_kernel<<<dim3(NN + XTRA, Bb), 256>>>(ctx, wemb, ns, out);
    finish_kernel<<<Bb, 256>>>(ns, out);
}